// round 6
// baseline (speedup 1.0000x reference)
#include <cuda_runtime.h>

#define NUM_USERS 400000

static __device__ int    g_first[NUM_USERS];
static __device__ int    g_last[NUM_USERS];
static __device__ double g_sum;

__global__ void init_kernel() {
    int i = blockIdx.x * blockDim.x + threadIdx.x;
    if (i < NUM_USERS) {
        g_first[i] = 0x7FFFFFFF;
        g_last[i]  = -1;
    }
    if (i == 0) g_sum = 0.0;
}

// One thread handles 4 int32 indexes (one int4 = 16B). Positions ascend with i;
// atomicMin/Max make the result order-independent. User ids are bounds-guarded
// so a dtype surprise degrades to a wrong answer instead of an illegal access.
__global__ void scatter_kernel(const int4* __restrict__ idx4, int n4) {
    int i = blockIdx.x * blockDim.x + threadIdx.x;
    if (i >= n4) return;
    int4 v = idx4[i];
    int p = 4 * i;
    int u;
    u = v.x; if ((unsigned)u < NUM_USERS) { atomicMin(&g_first[u], p);     atomicMax(&g_last[u], p); }
    u = v.y; if ((unsigned)u < NUM_USERS) { atomicMin(&g_first[u], p + 1); atomicMax(&g_last[u], p + 1); }
    u = v.z; if ((unsigned)u < NUM_USERS) { atomicMin(&g_first[u], p + 2); atomicMax(&g_last[u], p + 2); }
    u = v.w; if ((unsigned)u < NUM_USERS) { atomicMin(&g_first[u], p + 3); atomicMax(&g_last[u], p + 3); }
}

__global__ void scatter_tail_kernel(const int* __restrict__ idx, int n) {
    // handles n % 4 leftover elements (n = 8M -> none; kept for generality)
    int base = n & ~3;
    int r = n - base;
    if (blockIdx.x == 0 && threadIdx.x < r) {
        int p = base + threadIdx.x;
        int u = idx[p];
        if ((unsigned)u < NUM_USERS) {
            atomicMin(&g_first[u], p);
            atomicMax(&g_last[u],  p);
        }
    }
}

__global__ void compute_kernel(const float* __restrict__ pred,
                               const float* __restrict__ tgt, int n) {
    int u = blockIdx.x * blockDim.x + threadIdx.x;
    float ratio = 0.0f;
    if (u < NUM_USERS) {
        int f = g_first[u];
        int l = g_last[u];
        if (l <= f || (unsigned)f >= (unsigned)n || (unsigned)l >= (unsigned)n) {
            // count==0 (l=-1 < f=INT_MAX) or count==1 (l==f): dcg==idcg -> ratio 1
            ratio = 1.0f;
        } else {
            float p0 = __ldg(pred + f);
            float p1 = __ldg(pred + l);
            float t0 = __ldg(tgt  + f);
            float t1 = __ldg(tgt  + l);
            const float c = 0.6309297535714575f;  // 1/log2(3)
            float dcg  = (p0 >= p1) ? fmaf(t1, c, t0) : fmaf(t0, c, t1);
            float idcg = fmaf(fminf(t0, t1), c, fmaxf(t0, t1));
            ratio = dcg / idcg;
        }
    }
    // intra-warp reduce
    #pragma unroll
    for (int o = 16; o; o >>= 1)
        ratio += __shfl_down_sync(0xffffffffu, ratio, o);
    __shared__ float warp_sums[8];
    if ((threadIdx.x & 31) == 0) warp_sums[threadIdx.x >> 5] = ratio;
    __syncthreads();
    if (threadIdx.x < 8) {
        float s = warp_sums[threadIdx.x];
        #pragma unroll
        for (int o = 4; o; o >>= 1)
            s += __shfl_down_sync(0xffu, s, o);
        if (threadIdx.x == 0) atomicAdd(&g_sum, (double)s);
    }
}

__global__ void finalize_kernel(float* __restrict__ out) {
    out[0] = (float)(g_sum / (double)NUM_USERS);
}

extern "C" void kernel_launch(void* const* d_in, const int* in_sizes, int n_in,
                              void* d_out, int out_size) {
    const float* pred = (const float*)d_in[0];
    const float* tgt  = (const float*)d_in[1];
    const int*   idx  = (const int*)d_in[2];   // JAX x64 disabled: int64 request -> int32
    int n = in_sizes[2];
    float* out = (float*)d_out;

    const int T = 256;
    init_kernel<<<(NUM_USERS + T - 1) / T, T>>>();

    int n4 = n >> 2;
    scatter_kernel<<<(n4 + T - 1) / T, T>>>((const int4*)idx, n4);
    scatter_tail_kernel<<<1, 32>>>(idx, n);

    compute_kernel<<<(NUM_USERS + T - 1) / T, T>>>(pred, tgt, n);
    finalize_kernel<<<1, 1>>>(out);
}